// round 15
// baseline (speedup 1.0000x reference)
#include <cuda_runtime.h>
#include <cstdint>
#include <math.h>

#define KNODES 16
#define DMODEL 256
#define NSCALE 3
#define TAU_C 0.0001f
#define LN_EPS_C 1e-5f
#define MAXB 1024

// Both A- and B-chunks are 4096 floats (16 KB), stored in mma fragment order.
#define CHF 4096

// weight segment offsets in g_Wc (fragment-chunked, no padding)
#define OFF_WV 0
#define OFF_WE 196608
#define OFF_WO 393216
#define OFF_WF1 786432
#define OFF_WF2 1048576
#define WSRC 1310720

__device__ float g_xn[128 * 8 * CHF];            // A-frag chunks
__device__ float g_P [MAXB * KNODES * KNODES];
__device__ float g_mats[MAXB * NSCALE * 2 * 256];
__device__ float g_NE[(size_t)128 * 48 * CHF];   // A-frag chunks
__device__ float g_y [MAXB * KNODES * DMODEL];
__device__ float g_h [128 * 8 * CHF];            // A-frag chunks
__device__ float g_F [(size_t)128 * 32 * CHF];   // A-frag chunks
__device__ float g_Wc[WSRC];

// ---------------- helpers ----------------
__device__ __forceinline__ uint32_t f2tf32(float f) {
    uint32_t r; asm("cvt.rna.tf32.f32 %0, %1;" : "=r"(r) : "f"(f)); return r;
}
__device__ __forceinline__ float tf32r(float f) { return __uint_as_float(f2tf32(f)); }
__device__ __forceinline__ uint32_t su32(const void* p) {
    return (uint32_t)__cvta_generic_to_shared(p);
}
__device__ __forceinline__ void bulk_g2s(uint32_t dst, const void* src,
                                         uint32_t bytes, uint32_t mbar) {
    asm volatile(
        "cp.async.bulk.shared::cluster.global.mbarrier::complete_tx::bytes [%0], [%1], %2, [%3];"
        :: "r"(dst), "l"(src), "r"(bytes), "r"(mbar) : "memory");
}
#define MBAR_INIT(mb, c)  asm volatile("mbarrier.init.shared.b64 [%0], %1;" :: "r"(mb), "r"(c) : "memory")
#define MBAR_EXPECT(mb, b) asm volatile("mbarrier.arrive.expect_tx.shared.b64 _, [%0], %1;" :: "r"(mb), "r"(b) : "memory")
#define MBAR_WAIT(mb, p) do { \
    uint32_t _m = (mb), _p = (p), _d; \
    asm volatile("{\n\t.reg .pred q;\n\t" \
        "mbarrier.try_wait.parity.acquire.cta.shared::cta.b64 q, [%1], %2;\n\t" \
        "selp.b32 %0, 1, 0, q;\n\t}" : "=r"(_d) : "r"(_m), "r"(_p) : "memory"); \
    if (!_d) asm volatile("{\n\t.reg .pred q;\n\t" \
        "WL_%=:\n\tmbarrier.try_wait.parity.acquire.cta.shared::cta.b64 q, [%0], %1, 0x989680;\n\t" \
        "@q bra.uni WD_%=;\n\tbra.uni WL_%=;\n\tWD_%=:\n\t}" :: "r"(_m), "r"(_p) : "memory"); \
} while (0)

__device__ __forceinline__ float block_sum_256(float v) {
    __shared__ float red[8];
#pragma unroll
    for (int o = 16; o > 0; o >>= 1) v += __shfl_xor_sync(0xffffffffu, v, o);
    int lane = threadIdx.x & 31, w = threadIdx.x >> 5;
    if (lane == 0) red[w] = v;
    __syncthreads();
    float t = (threadIdx.x < 8) ? red[threadIdx.x] : 0.f;
    if (threadIdx.x < 32) {
#pragma unroll
        for (int o = 4; o > 0; o >>= 1) t += __shfl_xor_sync(0xffffffffu, t, o);
        if (threadIdx.x == 0) red[0] = t;
    }
    __syncthreads();
    float r = red[0];
    __syncthreads();
    return r;
}

// A-fragment index: warp-row wr=r>>5, i=(r>>4)&1, mbit=(r>>3)&1, gg=r&7
__device__ __forceinline__ int afrag_idx(int r, int kk) {
    int kc = kk >> 3, tt = kk & 3, r2 = (kk >> 2) & 1;
    int wr = r >> 5, i = (r >> 4) & 1, mbit = (r >> 3) & 1, gg = r & 7;
    return ((kc * 4 + wr) * 2 + i) * 128 + (4 * gg + tt) * 4 + (r2 * 2 + mbit);
}
// B-fragment index: warp-col wc=nn>>5, j=(nn>>3)&3, gg=nn&7
__device__ __forceinline__ int bfrag_idx(int kk, int nn) {
    int kc = kk >> 3, tt = kk & 3, r2 = (kk >> 2) & 1;
    int wc = nn >> 5, j = (nn >> 3) & 3, gg = nn & 7;
    return ((kc * 4 + wc) * 4 + j) * 64 + (4 * gg + tt) * 2 + r2;
}

// ---------------- weights -> fragment-chunked tf32 ----------------
__global__ void convert_w_kernel(const float* __restrict__ Wv, const float* __restrict__ We,
                                 const float* __restrict__ Wo, const float* __restrict__ Wf1,
                                 const float* __restrict__ Wf2, float* __restrict__ Wc) {
    int i = blockIdx.x * 256 + threadIdx.x;
    if (i >= WSRC) return;
    const float* src; int soff, doff, Kd, N;
    if (i < 196608)       { src = Wv;  soff = 0;       doff = OFF_WV;  Kd = 256;  N = 768;  }
    else if (i < 393216)  { src = We;  soff = 196608;  doff = OFF_WE;  Kd = 256;  N = 768;  }
    else if (i < 786432)  { src = Wo;  soff = 393216;  doff = OFF_WO;  Kd = 1536; N = 256;  }
    else if (i < 1048576) { src = Wf1; soff = 786432;  doff = OFF_WF1; Kd = 256;  N = 1024; }
    else                  { src = Wf2; soff = 1048576; doff = OFF_WF2; Kd = 1024; N = 256;  }
    int loc = i - soff;
    int k = loc / N, n = loc % N;
    int tn = n >> 7, ch = k >> 5;
    Wc[doff + (size_t)(tn * (Kd >> 5) + ch) * CHF + bfrag_idx(k & 31, n & 127)] =
        tf32r(src[loc]);
}

// ---------------- LN1 + P  (xn -> A-frag chunks) ----------------
__global__ void ln1_p_kernel(const float* __restrict__ x,
                             const float* __restrict__ g, const float* __restrict__ bb,
                             const float* __restrict__ Wg, const float* __restrict__ bg,
                             float* __restrict__ xn_out, float* __restrict__ P_out) {
    int row = blockIdx.x;
    int t = threadIdx.x;
    float v = x[(size_t)row * DMODEL + t];
    float mean = block_sum_256(v) * (1.f / DMODEL);
    float d = v - mean;
    float var = block_sum_256(d * d) * (1.f / DMODEL);
    float xn = d * rsqrtf(var + LN_EPS_C) * g[t] + bb[t];
    int tm = row >> 7, r = row & 127, ch = t >> 5;
    xn_out[(size_t)(tm * 8 + ch) * CHF + afrag_idx(r, t & 31)] = tf32r(xn);

    __shared__ float sxn[256];
    __shared__ float part[256];
    sxn[t] = xn;
    __syncthreads();
    int c = t & 15, seg = t >> 4;
    float p = 0.f;
    int d0 = seg * 16;
#pragma unroll
    for (int i = 0; i < 16; i++) p += sxn[d0 + i] * Wg[(d0 + i) * 16 + c];
    part[seg * 16 + c] = p;
    __syncthreads();
    if (t < 16) {
        float acc = bg[t];
#pragma unroll
        for (int s = 0; s < 16; s++) acc += part[s * 16 + t];
        P_out[(size_t)row * 16 + t] = acc;
    }
}

// ---------------- LN2 (y row-major -> h A-frag chunks) ----------------
__global__ void ln_kernel(const float* __restrict__ x,
                          const float* __restrict__ g, const float* __restrict__ bb,
                          float* __restrict__ out) {
    int row = blockIdx.x;
    int t = threadIdx.x;
    float v = x[(size_t)row * DMODEL + t];
    float mean = block_sum_256(v) * (1.f / DMODEL);
    float d = v - mean;
    float var = block_sum_256(d * d) * (1.f / DMODEL);
    int tm = row >> 7, r = row & 127, ch = t >> 5;
    out[(size_t)(tm * 8 + ch) * CHF + afrag_idx(r, t & 31)] =
        tf32r(d * rsqrtf(var + LN_EPS_C) * g[t] + bb[t]);
}

// ---------------- per-(b,s) 16x16 operators ----------------
__global__ void build_mats_kernel(const float* __restrict__ P,
                                  const float* __restrict__ mask,
                                  const float* __restrict__ log_scales,
                                  float* __restrict__ mats) {
    int b = blockIdx.x;
    int tid = threadIdx.x;
    __shared__ float sP[256], sm[16], sp2[16], sDsq[256], saff[256], stw[16];
    sP[tid] = P[(size_t)b * 256 + tid];
    if (tid < 16) sm[tid] = mask[(size_t)b * 16 + tid];
    __syncthreads();
    int k = tid >> 4, l = tid & 15;
    if (tid < 16) {
        float s = 0.f;
#pragma unroll
        for (int c = 0; c < 16; c++) s += sP[tid * 16 + c] * sP[tid * 16 + c];
        sp2[tid] = s;
    }
    __syncthreads();
    {
        float dt = 0.f;
#pragma unroll
        for (int c = 0; c < 16; c++) dt += sP[k * 16 + c] * sP[l * 16 + c];
        sDsq[tid] = fmaxf(sp2[k] + sp2[l] - 2.f * dt, 0.f) * sm[k] * sm[l];
    }
    __syncthreads();
    for (int s = 0; s < NSCALE; s++) {
        float denom = 2.f * expf(2.f * log_scales[s]) + 1e-8f;
        saff[tid] = expf(-sDsq[tid] / denom) * sm[k] * sm[l];
        __syncthreads();
        float l0;
        if (k == l) {
            float srow = 0.f;
#pragma unroll
            for (int j = 0; j < 16; j++) if (j != k) srow += saff[k * 16 + j];
            l0 = srow + TAU_C;
        } else l0 = -saff[tid];
        if (tid < 16) {
            float tsum = 0.f;
            int j = tid;
            for (int i = 0; i < j; i++)
                for (int k2 = j + 1; k2 < 16; k2++)
                    tsum += saff[i * 16 + j] * saff[j * 16 + k2] * saff[i * 16 + k2];
            stw[tid] = tsum;
        }
        __syncthreads();
        float nv = 0.f;
#pragma unroll
        for (int kp = 0; kp < 16; kp++) {
            float dk = (kp == k) ? (2.f * k - 15.f) : ((kp > k) ? 1.f : -1.f);
            float dl = (kp == l) ? (2.f * l - 15.f) : ((kp > l) ? 1.f : -1.f);
            nv += sm[kp] * dk * dl;
        }
        nv += (k == l) ? (4.f * stw[k] + 15.f * TAU_C) : TAU_C;
        size_t base = ((size_t)b * NSCALE + s) * 512;
        mats[base + tid] = l0;
        mats[base + 256 + tid] = nv;
        __syncthreads();
    }
}

// ---------------- tf32 mma GEMM: 512 thr, 16 warps of 32x32, ring-3 ---------
#define STAGE_BYTES 32768
#define STAGE_U32   8192
#define SMEM_BYTES  (3 * STAGE_BYTES)   // 98304

__global__ __launch_bounds__(512, 2) void tf32_gemm5(
    const float* __restrict__ A,
    const float* __restrict__ B1, const float* __restrict__ B2, int N1,
    float* __restrict__ C,
    const float* __restrict__ bias1, const float* __restrict__ bias2,
    float s1, float s2,
    const float* __restrict__ resid,
    const float* __restrict__ matsG, int applyMats,
    int M, int nChK, int ldc, int outChunk, int nChOut, int doGelu)
{
    extern __shared__ uint32_t sm_[];
    __shared__ __align__(8) uint64_t mbarStore[3];

    const int tid  = threadIdx.x;
    const int warp = tid >> 5, lane = tid & 31;
    const int g = lane >> 2, t = lane & 3;
    const int wr = warp >> 2;           // m-group (0..3), rows wr*32..+31
    const int wc = warp & 3;            // n-group (0..3), cols wc*32..+31
    const int bm = blockIdx.y << 7;
    const int bnG = blockIdx.x << 7;
    const uint32_t base = su32(sm_);
    const uint32_t mbF = su32(&mbarStore[0]);

    const float* Bseg; const float* bias; float bsc; int bcol;
    if (bnG < N1) { Bseg = B1; bias = bias1; bsc = s1; bcol = bnG; }
    else          { Bseg = B2; bias = bias2; bsc = s2; bcol = bnG - N1; }
    const float* At = A + (size_t)(bm >> 7) * nChK * CHF;
    const float* Bt = Bseg + (size_t)(bcol >> 7) * nChK * CHF;

    if (tid == 0)
        for (int i = 0; i < 3; i++) MBAR_INIT(mbF + 8 * i, 1);
    __syncthreads();

#define ISSUE(s_, ch_) do { \
    if (tid == 0) { \
        MBAR_EXPECT(mbF + 8 * (s_), (uint32_t)STAGE_BYTES); \
        bulk_g2s(base + (s_) * STAGE_BYTES, At + (size_t)(ch_) * CHF, CHF * 4, mbF + 8 * (s_)); \
        bulk_g2s(base + (s_) * STAGE_BYTES + CHF * 4, Bt + (size_t)(ch_) * CHF, CHF * 4, mbF + 8 * (s_)); \
    } \
} while (0)

    ISSUE(0, 0);
    if (nChK > 1) ISSUE(1, 1);

    float acc[2][4][4];
#pragma unroll
    for (int i = 0; i < 2; i++)
#pragma unroll
        for (int j = 0; j < 4; j++)
#pragma unroll
            for (int r = 0; r < 4; r++) acc[i][j][r] = 0.f;

    for (int ch = 0; ch < nChK; ch++) {
        const int s = ch % 3;
        MBAR_WAIT(mbF + 8 * s, (ch / 3) & 1);
        __syncthreads();
        if (ch + 2 < nChK) ISSUE((ch + 2) % 3, ch + 2);

        const uint4* As4 = (const uint4*)(sm_ + s * STAGE_U32);
        const uint2* Bs2 = (const uint2*)(sm_ + s * STAGE_U32 + CHF);

#pragma unroll
        for (int kc = 0; kc < 4; kc++) {
            uint4 av[2];
            uint2 bv[4];
#pragma unroll
            for (int i = 0; i < 2; i++)
                av[i] = As4[((kc * 4 + wr) * 2 + i) * 32 + lane];
#pragma unroll
            for (int j = 0; j < 4; j++)
                bv[j] = Bs2[((kc * 4 + wc) * 4 + j) * 32 + lane];
#pragma unroll
            for (int i = 0; i < 2; i++)
#pragma unroll
                for (int j = 0; j < 4; j++) {
                    asm volatile(
                        "mma.sync.aligned.m16n8k8.row.col.f32.tf32.tf32.f32 "
                        "{%0,%1,%2,%3}, {%4,%5,%6,%7}, {%8,%9}, {%0,%1,%2,%3};"
                        : "+f"(acc[i][j][0]), "+f"(acc[i][j][1]),
                          "+f"(acc[i][j][2]), "+f"(acc[i][j][3])
                        : "r"(av[i].x), "r"(av[i].y), "r"(av[i].z), "r"(av[i].w),
                          "r"(bv[j].x), "r"(bv[j].y));
                }
        }
    }
#undef ISSUE

    const int tmO = bm >> 7;
    if (applyMats) {
        // tensor-core 16x16 Hodge apply:  out_b = M_b @ (acc_b + bias)
        float (*Cs)[136] = (float (*)[136])sm_;
        float* matS = (float*)(sm_ + 128 * 136);
        __syncthreads();
#pragma unroll
        for (int i = 0; i < 2; i++) {
            int ml = (wr << 5) + (i << 4) + g;
#pragma unroll
            for (int j = 0; j < 4; j++) {
                int nl = (wc << 5) + (j << 3) + 2 * t;
                int bc = bcol + nl;
                float b0v = bsc * bias[bc];
                float b1v = bsc * bias[bc + 1];
#pragma unroll
                for (int rr = 0; rr < 2; rr++) {
                    float2 vv = make_float2(tf32r(acc[i][j][rr * 2 + 0] + b0v),
                                            tf32r(acc[i][j][rr * 2 + 1] + b1v));
                    *(float2*)&Cs[ml + rr * 8][nl] = vv;
                }
            }
        }
        int isN = (bnG >= 768) ? 1 : 0;
        int sgrp = (isN ? (bnG - 768) : bnG) >> 8;
        int b0 = bm >> 4;
        for (int i = tid; i < 2048; i += 512) {
            int bb = i >> 8, e = i & 255;
            matS[i] = tf32r(matsG[((size_t)(b0 + bb) * NSCALE + sgrp) * 512 + (isN << 8) + e]);
        }
        __syncthreads();
        // warp pair: bb = warp&7 (batch), nh = warp>>3 (column half)
        const int bb = warp & 7;
        const int nh = warp >> 3;
        const float* Mb = matS + (bb << 8);
        const int rowBase = bb << 4;
        const int wrO = bb >> 1, iO = bb & 1;
        uint32_t a[2][4];
#pragma unroll
        for (int ks = 0; ks < 2; ks++) {
            int kk = ks << 3;
            a[ks][0] = __float_as_uint(Mb[(g << 4) + kk + t]);
            a[ks][1] = __float_as_uint(Mb[((g + 8) << 4) + kk + t]);
            a[ks][2] = __float_as_uint(Mb[(g << 4) + kk + t + 4]);
            a[ks][3] = __float_as_uint(Mb[((g + 8) << 4) + kk + t + 4]);
        }
        if (bm + rowBase < M) {
#pragma unroll
            for (int nn2 = 0; nn2 < 8; nn2++) {
                int nn = (nh << 3) + nn2;
                int n0 = nn << 3;
                float v0 = 0.f, v1 = 0.f, v2 = 0.f, v3 = 0.f;
#pragma unroll
                for (int ks = 0; ks < 2; ks++) {
                    uint32_t b0r = __float_as_uint(Cs[rowBase + (ks << 3) + t][n0 + g]);
                    uint32_t b1r = __float_as_uint(Cs[rowBase + (ks << 3) + t + 4][n0 + g]);
                    asm volatile(
                        "mma.sync.aligned.m16n8k8.row.col.f32.tf32.tf32.f32 "
                        "{%0,%1,%2,%3}, {%4,%5,%6,%7}, {%8,%9}, {%0,%1,%2,%3};"
                        : "+f"(v0), "+f"(v1), "+f"(v2), "+f"(v3)
                        : "r"(a[ks][0]), "r"(a[ks][1]), "r"(a[ks][2]), "r"(a[ks][3]),
                          "r"(b0r), "r"(b1r));
                }
                // A-frag chunked write into NE: cols G,G+1; rows rowBase+g(+8)
                int G = bnG + n0 + 2 * t;
                int chO = G >> 5, kk2 = G & 31;
                int kcO = kk2 >> 3, tt0 = kk2 & 3, r2O = (kk2 >> 2) & 1;
                size_t cb = (size_t)(tmO * nChOut + chO) * CHF;
                int ib = ((kcO * 4 + wrO) * 2 + iO) * 128 + (4 * g + tt0) * 4 + r2O * 2;
                C[cb + ib]     = tf32r(v0);       // row mbit0, col G
                C[cb + ib + 4] = tf32r(v1);       // row mbit0, col G+1
                C[cb + ib + 1] = tf32r(v2);       // row mbit1, col G
                C[cb + ib + 5] = tf32r(v3);       // row mbit1, col G+1
            }
        }
        return;
    }

    // generic epilogue
#pragma unroll
    for (int i = 0; i < 2; i++) {
        int m0 = bm + (wr << 5) + (i << 4) + g;
#pragma unroll
        for (int j = 0; j < 4; j++) {
            int nl = (wc << 5) + (j << 3) + 2 * t;
            int n0 = bnG + nl;
#pragma unroll
            for (int rr = 0; rr < 2; rr++) {
                int m = m0 + rr * 8;
                if (m >= M) continue;
                float v0 = acc[i][j][rr * 2 + 0];
                float v1 = acc[i][j][rr * 2 + 1];
                int bc = bcol + nl;
                v0 += bsc * bias[bc];
                v1 += bsc * bias[bc + 1];
                if (resid) {
                    v0 += resid[(size_t)m * ldc + n0];
                    v1 += resid[(size_t)m * ldc + n0 + 1];
                }
                if (doGelu) {
                    v0 = 0.5f * v0 * (1.0f + erff(v0 * 0.70710678118654752f));
                    v1 = 0.5f * v1 * (1.0f + erff(v1 * 0.70710678118654752f));
                }
                if (outChunk) {
                    int chO = n0 >> 5, kk2 = n0 & 31;
                    int kcO = kk2 >> 3, tt0 = kk2 & 3, r2O = (kk2 >> 2) & 1;
                    size_t cb = (size_t)((m >> 7) * nChOut + chO) * CHF;
                    int ib = ((kcO * 4 + wr) * 2 + i) * 128 + (4 * g + tt0) * 4 + r2O * 2 + rr;
                    C[cb + ib]     = tf32r(v0);
                    C[cb + ib + 4] = tf32r(v1);
                } else {
                    *(float2*)(C + (size_t)m * ldc + n0) = make_float2(v0, v1);
                }
            }
        }
    }
}

// ---------------- launch ----------------
extern "C" void kernel_launch(void* const* d_in, const int* in_sizes, int n_in,
                              void* d_out, int out_size) {
    const float* x          = (const float*)d_in[0];
    const float* mask       = (const float*)d_in[1];
    const float* Wg         = (const float*)d_in[2];
    const float* bg         = (const float*)d_in[3];
    const float* log_scales = (const float*)d_in[4];
    const float* Wv         = (const float*)d_in[5];
    const float* bv         = (const float*)d_in[6];
    const float* We         = (const float*)d_in[7];
    const float* be         = (const float*)d_in[8];
    const float* Wo         = (const float*)d_in[9];
    const float* bo         = (const float*)d_in[10];
    const float* ln1g       = (const float*)d_in[11];
    const float* ln1b       = (const float*)d_in[12];
    const float* ln2g       = (const float*)d_in[13];
    const float* ln2b       = (const float*)d_in[14];
    const float* Wf1        = (const float*)d_in[15];
    const float* bf1        = (const float*)d_in[16];
    const float* Wf2        = (const float*)d_in[17];
    const float* bf2        = (const float*)d_in[18];
    float* out = (float*)d_out;

    int B = in_sizes[0] / (KNODES * DMODEL);
    int M = B * KNODES;
    int gy = (M + 127) / 128;

    void *p_xn, *p_P, *p_mats, *p_NE, *p_y, *p_h, *p_F, *p_Wc;
    cudaGetSymbolAddress(&p_xn, g_xn);
    cudaGetSymbolAddress(&p_P, g_P);
    cudaGetSymbolAddress(&p_mats, g_mats);
    cudaGetSymbolAddress(&p_NE, g_NE);
    cudaGetSymbolAddress(&p_y, g_y);
    cudaGetSymbolAddress(&p_h, g_h);
    cudaGetSymbolAddress(&p_F, g_F);
    cudaGetSymbolAddress(&p_Wc, g_Wc);
    float* xn = (float*)p_xn;   float* Pm = (float*)p_P;
    float* mats = (float*)p_mats;
    float* NE = (float*)p_NE;   float* y = (float*)p_y;
    float* h = (float*)p_h;     float* F = (float*)p_F;
    float* Wc = (float*)p_Wc;

    static int attrDone = 0;
    if (!attrDone) {
        cudaFuncSetAttribute(tf32_gemm5, cudaFuncAttributeMaxDynamicSharedMemorySize, SMEM_BYTES);
        attrDone = 1;
    }
    const int BIGN = 1 << 28;

    convert_w_kernel<<<(WSRC + 255) / 256, 256>>>(Wv, We, Wo, Wf1, Wf2, Wc);
    ln1_p_kernel<<<M, 256>>>(x, ln1g, ln1b, Wg, bg, xn, Pm);
    build_mats_kernel<<<B, 256>>>(Pm, mask, log_scales, mats);
    // NE = blockdiag(16x16) x [xn@Wv + bv | xn@We + 0.5*be]  (A-frag out, 48 ch)
    tf32_gemm5<<<dim3(12, gy), 512, SMEM_BYTES>>>(
        xn, Wc + OFF_WV, Wc + OFF_WE, 768,
        NE, bv, be, 1.0f, 0.5f, nullptr, mats, 1,
        M, 8, 0, 1, 48, 0);
    // y = x + NE@Wo + bo  (row-major out)
    tf32_gemm5<<<dim3(2, gy), 512, SMEM_BYTES>>>(
        NE, Wc + OFF_WO, Wc + OFF_WO, BIGN,
        y, bo, bo, 1.0f, 1.0f, x, nullptr, 0,
        M, 48, 256, 0, 0, 0);
    ln_kernel<<<M, 256>>>(y, ln2g, ln2b, h);
    // F = gelu(h@Wf1 + bf1)  (A-frag out, 32 ch)
    tf32_gemm5<<<dim3(8, gy), 512, SMEM_BYTES>>>(
        h, Wc + OFF_WF1, Wc + OFF_WF1, BIGN,
        F, bf1, bf1, 1.0f, 1.0f, nullptr, nullptr, 0,
        M, 8, 0, 1, 32, 1);
    // out = y + F@Wf2 + bf2  (row-major out)
    tf32_gemm5<<<dim3(2, gy), 512, SMEM_BYTES>>>(
        F, Wc + OFF_WF2, Wc + OFF_WF2, BIGN,
        out, bf2, bf2, 1.0f, 1.0f, y, nullptr, 0,
        M, 32, 256, 0, 0, 0);
}

// round 16
// speedup vs baseline: 1.3680x; 1.3680x over previous
#include <cuda_runtime.h>
#include <cuda_fp16.h>
#include <cstdint>
#include <math.h>

#define KNODES 16
#define DMODEL 256
#define NSCALE 3
#define TAU_C 0.0001f
#define LN_EPS_C 1e-5f
#define MAXB 1024

// A- and B-chunks: 128(rows/cols) x 32(k) fp16 = 4096 halves = 8 KB, frag order
#define CHH 4096

// weight segment offsets in g_Wc (halves)
#define OFF_WV 0
#define OFF_WE 196608
#define OFF_WO 393216
#define OFF_WF1 786432
#define OFF_WF2 1048576
#define WSRC 1310720

__device__ __half g_xn[128 * 8 * CHH];
__device__ float  g_P [MAXB * KNODES * KNODES];
__device__ float  g_mats[MAXB * NSCALE * 2 * 256];
__device__ __half g_NE[(size_t)128 * 48 * CHH];
__device__ float  g_y [MAXB * KNODES * DMODEL];
__device__ __half g_h [128 * 8 * CHH];
__device__ __half g_F [(size_t)128 * 32 * CHH];
__device__ __half g_Wc[WSRC];

// ---------------- helpers ----------------
__device__ __forceinline__ uint32_t su32(const void* p) {
    return (uint32_t)__cvta_generic_to_shared(p);
}
__device__ __forceinline__ void bulk_g2s(uint32_t dst, const void* src,
                                         uint32_t bytes, uint32_t mbar) {
    asm volatile(
        "cp.async.bulk.shared::cluster.global.mbarrier::complete_tx::bytes [%0], [%1], %2, [%3];"
        :: "r"(dst), "l"(src), "r"(bytes), "r"(mbar) : "memory");
}
#define MBAR_INIT(mb, c)  asm volatile("mbarrier.init.shared.b64 [%0], %1;" :: "r"(mb), "r"(c) : "memory")
#define MBAR_EXPECT(mb, b) asm volatile("mbarrier.arrive.expect_tx.shared.b64 _, [%0], %1;" :: "r"(mb), "r"(b) : "memory")
#define MBAR_WAIT(mb, p) do { \
    uint32_t _m = (mb), _p = (p), _d; \
    asm volatile("{\n\t.reg .pred q;\n\t" \
        "mbarrier.try_wait.parity.acquire.cta.shared::cta.b64 q, [%1], %2;\n\t" \
        "selp.b32 %0, 1, 0, q;\n\t}" : "=r"(_d) : "r"(_m), "r"(_p) : "memory"); \
    if (!_d) asm volatile("{\n\t.reg .pred q;\n\t" \
        "WL_%=:\n\tmbarrier.try_wait.parity.acquire.cta.shared::cta.b64 q, [%0], %1, 0x989680;\n\t" \
        "@q bra.uni WD_%=;\n\tbra.uni WL_%=;\n\tWD_%=:\n\t}" :: "r"(_m), "r"(_p) : "memory"); \
} while (0)

#define MMA16(c0,c1,c2,c3, a0,a1,a2,a3, b0,b1) \
    asm volatile("mma.sync.aligned.m16n8k16.row.col.f32.f16.f16.f32 " \
        "{%0,%1,%2,%3}, {%4,%5,%6,%7}, {%8,%9}, {%0,%1,%2,%3};" \
        : "+f"(c0), "+f"(c1), "+f"(c2), "+f"(c3) \
        : "r"(a0), "r"(a1), "r"(a2), "r"(a3), "r"(b0), "r"(b1))

__device__ __forceinline__ float block_sum_256(float v) {
    __shared__ float red[8];
#pragma unroll
    for (int o = 16; o > 0; o >>= 1) v += __shfl_xor_sync(0xffffffffu, v, o);
    int lane = threadIdx.x & 31, w = threadIdx.x >> 5;
    if (lane == 0) red[w] = v;
    __syncthreads();
    float t = (threadIdx.x < 8) ? red[threadIdx.x] : 0.f;
    if (threadIdx.x < 32) {
#pragma unroll
        for (int o = 4; o > 0; o >>= 1) t += __shfl_xor_sync(0xffffffffu, t, o);
        if (threadIdx.x == 0) red[0] = t;
    }
    __syncthreads();
    float r = red[0];
    __syncthreads();
    return r;
}

// fp16 m16n8k16 fragment half-index for A element (r=row&127, kk=k&31)
__device__ __forceinline__ int afrag_idx(int r, int kk) {
    int ks = kk >> 4, tpos = (kk >> 1) & 3, khigh = (kk >> 3) & 1, par = kk & 1;
    int wr = r >> 5, i = (r >> 4) & 1, mbit = (r >> 3) & 1, gg = r & 7;
    return ((((ks * 4 + wr) * 2 + i) * 128 + (gg * 4 + tpos) * 4 + (khigh * 2 + mbit)) << 1) | par;
}
// B element (kk=k&31, nn=n&127)
__device__ __forceinline__ int bfrag_idx(int kk, int nn) {
    int ks = kk >> 4, tpos = (kk >> 1) & 3, khigh = (kk >> 3) & 1, par = kk & 1;
    int wc = nn >> 5, j = (nn >> 3) & 3, gg = nn & 7;
    return ((((ks * 4 + wc) * 4 + j) * 64 + (gg * 4 + tpos) * 2 + khigh) << 1) | par;
}

// ---------------- weights -> fragment-chunked fp16 ----------------
__global__ void convert_w_kernel(const float* __restrict__ Wv, const float* __restrict__ We,
                                 const float* __restrict__ Wo, const float* __restrict__ Wf1,
                                 const float* __restrict__ Wf2, __half* __restrict__ Wc) {
    int i = blockIdx.x * 256 + threadIdx.x;
    if (i >= WSRC) return;
    const float* src; int soff, doff, Kd, N;
    if (i < 196608)       { src = Wv;  soff = 0;       doff = OFF_WV;  Kd = 256;  N = 768;  }
    else if (i < 393216)  { src = We;  soff = 196608;  doff = OFF_WE;  Kd = 256;  N = 768;  }
    else if (i < 786432)  { src = Wo;  soff = 393216;  doff = OFF_WO;  Kd = 1536; N = 256;  }
    else if (i < 1048576) { src = Wf1; soff = 786432;  doff = OFF_WF1; Kd = 256;  N = 1024; }
    else                  { src = Wf2; soff = 1048576; doff = OFF_WF2; Kd = 1024; N = 256;  }
    int loc = i - soff;
    int k = loc / N, n = loc % N;
    int tn = n >> 7, ch = k >> 5;
    Wc[doff + (size_t)(tn * (Kd >> 5) + ch) * CHH + bfrag_idx(k & 31, n & 127)] =
        __float2half(src[loc]);
}

// ---------------- LN1 + P  (xn -> A-frag fp16 chunks) ----------------
__global__ void ln1_p_kernel(const float* __restrict__ x,
                             const float* __restrict__ g, const float* __restrict__ bb,
                             const float* __restrict__ Wg, const float* __restrict__ bg,
                             __half* __restrict__ xn_out, float* __restrict__ P_out) {
    int row = blockIdx.x;
    int t = threadIdx.x;
    float v = x[(size_t)row * DMODEL + t];
    float mean = block_sum_256(v) * (1.f / DMODEL);
    float d = v - mean;
    float var = block_sum_256(d * d) * (1.f / DMODEL);
    float xn = d * rsqrtf(var + LN_EPS_C) * g[t] + bb[t];
    int tm = row >> 7, r = row & 127, ch = t >> 5;
    xn_out[(size_t)(tm * 8 + ch) * CHH + afrag_idx(r, t & 31)] = __float2half(xn);

    __shared__ float sxn[256];
    __shared__ float part[256];
    sxn[t] = xn;
    __syncthreads();
    int c = t & 15, seg = t >> 4;
    float p = 0.f;
    int d0 = seg * 16;
#pragma unroll
    for (int i = 0; i < 16; i++) p += sxn[d0 + i] * Wg[(d0 + i) * 16 + c];
    part[seg * 16 + c] = p;
    __syncthreads();
    if (t < 16) {
        float acc = bg[t];
#pragma unroll
        for (int s = 0; s < 16; s++) acc += part[s * 16 + t];
        P_out[(size_t)row * 16 + t] = acc;
    }
}

// ---------------- LN2 (y row-major -> h fp16 A-frag chunks) ----------------
__global__ void ln_kernel(const float* __restrict__ x,
                          const float* __restrict__ g, const float* __restrict__ bb,
                          __half* __restrict__ out) {
    int row = blockIdx.x;
    int t = threadIdx.x;
    float v = x[(size_t)row * DMODEL + t];
    float mean = block_sum_256(v) * (1.f / DMODEL);
    float d = v - mean;
    float var = block_sum_256(d * d) * (1.f / DMODEL);
    int tm = row >> 7, r = row & 127, ch = t >> 5;
    out[(size_t)(tm * 8 + ch) * CHH + afrag_idx(r, t & 31)] =
        __float2half(d * rsqrtf(var + LN_EPS_C) * g[t] + bb[t]);
}

// ---------------- per-(b,s) 16x16 operators ----------------
__global__ void build_mats_kernel(const float* __restrict__ P,
                                  const float* __restrict__ mask,
                                  const float* __restrict__ log_scales,
                                  float* __restrict__ mats) {
    int b = blockIdx.x;
    int tid = threadIdx.x;
    __shared__ float sP[256], sm[16], sp2[16], sDsq[256], saff[256], stw[16];
    sP[tid] = P[(size_t)b * 256 + tid];
    if (tid < 16) sm[tid] = mask[(size_t)b * 16 + tid];
    __syncthreads();
    int k = tid >> 4, l = tid & 15;
    if (tid < 16) {
        float s = 0.f;
#pragma unroll
        for (int c = 0; c < 16; c++) s += sP[tid * 16 + c] * sP[tid * 16 + c];
        sp2[tid] = s;
    }
    __syncthreads();
    {
        float dt = 0.f;
#pragma unroll
        for (int c = 0; c < 16; c++) dt += sP[k * 16 + c] * sP[l * 16 + c];
        sDsq[tid] = fmaxf(sp2[k] + sp2[l] - 2.f * dt, 0.f) * sm[k] * sm[l];
    }
    __syncthreads();
    for (int s = 0; s < NSCALE; s++) {
        float denom = 2.f * expf(2.f * log_scales[s]) + 1e-8f;
        saff[tid] = expf(-sDsq[tid] / denom) * sm[k] * sm[l];
        __syncthreads();
        float l0;
        if (k == l) {
            float srow = 0.f;
#pragma unroll
            for (int j = 0; j < 16; j++) if (j != k) srow += saff[k * 16 + j];
            l0 = srow + TAU_C;
        } else l0 = -saff[tid];
        if (tid < 16) {
            float tsum = 0.f;
            int j = tid;
            for (int i = 0; i < j; i++)
                for (int k2 = j + 1; k2 < 16; k2++)
                    tsum += saff[i * 16 + j] * saff[j * 16 + k2] * saff[i * 16 + k2];
            stw[tid] = tsum;
        }
        __syncthreads();
        float nv = 0.f;
#pragma unroll
        for (int kp = 0; kp < 16; kp++) {
            float dk = (kp == k) ? (2.f * k - 15.f) : ((kp > k) ? 1.f : -1.f);
            float dl = (kp == l) ? (2.f * l - 15.f) : ((kp > l) ? 1.f : -1.f);
            nv += sm[kp] * dk * dl;
        }
        nv += (k == l) ? (4.f * stw[k] + 15.f * TAU_C) : TAU_C;
        size_t base = ((size_t)b * NSCALE + s) * 512;
        mats[base + tid] = l0;
        mats[base + 256 + tid] = nv;
        __syncthreads();
    }
}

// ---------------- fp16 mma GEMM: 512 thr, 16 warps of 32x32, ring-3 ---------
#define STAGE_BYTES 16384
#define STAGE_U32   4096
#define SMEM_BYTES  (3 * STAGE_BYTES)   // 49152

__global__ __launch_bounds__(512, 2) void fp16_gemm(
    const __half* __restrict__ A,
    const __half* __restrict__ B1, const __half* __restrict__ B2, int N1,
    float* __restrict__ C, __half* __restrict__ Ch,
    const float* __restrict__ bias1, const float* __restrict__ bias2,
    float s1, float s2,
    const float* __restrict__ resid,
    const float* __restrict__ matsG, int applyMats,
    int M, int nChK, int ldc, int outChunk, int nChOut, int doGelu)
{
    extern __shared__ uint32_t sm_[];
    __shared__ __align__(8) uint64_t mbarStore[3];

    const int tid  = threadIdx.x;
    const int warp = tid >> 5, lane = tid & 31;
    const int g = lane >> 2, t = lane & 3;
    const int wr = warp >> 2;
    const int wc = warp & 3;
    const int bm = blockIdx.y << 7;
    const int bnG = blockIdx.x << 7;
    const uint32_t base = su32(sm_);
    const uint32_t mbF = su32(&mbarStore[0]);

    const __half* Bseg; const float* bias; float bsc; int bcol;
    if (bnG < N1) { Bseg = B1; bias = bias1; bsc = s1; bcol = bnG; }
    else          { Bseg = B2; bias = bias2; bsc = s2; bcol = bnG - N1; }
    const __half* At = A + (size_t)(bm >> 7) * nChK * CHH;
    const __half* Bt = Bseg + (size_t)(bcol >> 7) * nChK * CHH;

    if (tid == 0)
        for (int i = 0; i < 3; i++) MBAR_INIT(mbF + 8 * i, 1);
    __syncthreads();

#define ISSUE(s_, ch_) do { \
    if (tid == 0) { \
        MBAR_EXPECT(mbF + 8 * (s_), (uint32_t)STAGE_BYTES); \
        bulk_g2s(base + (s_) * STAGE_BYTES, At + (size_t)(ch_) * CHH, CHH * 2, mbF + 8 * (s_)); \
        bulk_g2s(base + (s_) * STAGE_BYTES + CHH * 2, Bt + (size_t)(ch_) * CHH, CHH * 2, mbF + 8 * (s_)); \
    } \
} while (0)

    ISSUE(0, 0);
    if (nChK > 1) ISSUE(1, 1);

    float acc[2][4][4];
#pragma unroll
    for (int i = 0; i < 2; i++)
#pragma unroll
        for (int j = 0; j < 4; j++)
#pragma unroll
            for (int r = 0; r < 4; r++) acc[i][j][r] = 0.f;

    for (int ch = 0; ch < nChK; ch++) {
        const int s = ch % 3;
        MBAR_WAIT(mbF + 8 * s, (ch / 3) & 1);
        __syncthreads();
        if (ch + 2 < nChK) ISSUE((ch + 2) % 3, ch + 2);

        const uint4* As4 = (const uint4*)(sm_ + s * STAGE_U32);
        const uint2* Bs2 = (const uint2*)(sm_ + s * STAGE_U32 + 2048);

#pragma unroll
        for (int ks = 0; ks < 2; ks++) {
            uint4 av[2];
            uint2 bv[4];
#pragma unroll
            for (int i = 0; i < 2; i++)
                av[i] = As4[((ks * 4 + wr) * 2 + i) * 32 + lane];
#pragma unroll
            for (int j = 0; j < 4; j++)
                bv[j] = Bs2[((ks * 4 + wc) * 4 + j) * 32 + lane];
#pragma unroll
            for (int i = 0; i < 2; i++)
#pragma unroll
                for (int j = 0; j < 4; j++)
                    MMA16(acc[i][j][0], acc[i][j][1], acc[i][j][2], acc[i][j][3],
                          av[i].x, av[i].y, av[i].z, av[i].w, bv[j].x, bv[j].y);
        }
    }
#undef ISSUE

    const int tmO = bm >> 7;
    if (applyMats) {
        // fp16 tensor-core 16x16 Hodge apply:  out_b = M_b @ (acc_b + bias)
        __half* CsH = (__half*)sm_;                 // [col][136] halves
        __half* matS = (__half*)(sm_ + (128 * 136) / 2);
        __syncthreads();
#pragma unroll
        for (int i = 0; i < 2; i++) {
            int ml = (wr << 5) + (i << 4) + g;
#pragma unroll
            for (int j = 0; j < 4; j++) {
                int nl = (wc << 5) + (j << 3) + 2 * t;
                int bc = bcol + nl;
                float b0v = bsc * bias[bc];
                float b1v = bsc * bias[bc + 1];
#pragma unroll
                for (int rr = 0; rr < 2; rr++) {
                    int row = ml + rr * 8;
                    CsH[nl * 136 + row]       = __float2half(acc[i][j][rr * 2 + 0] + b0v);
                    CsH[(nl + 1) * 136 + row] = __float2half(acc[i][j][rr * 2 + 1] + b1v);
                }
            }
        }
        int isN = (bnG >= 768) ? 1 : 0;
        int sgrp = (isN ? (bnG - 768) : bnG) >> 8;
        int b0 = bm >> 4;
        for (int i = tid; i < 2048; i += 512) {
            int bb2 = i >> 8, e = i & 255;
            matS[i] = __float2half(
                matsG[((size_t)(b0 + bb2) * NSCALE + sgrp) * 512 + (isN << 8) + e]);
        }
        __syncthreads();
        const int bb = warp & 7;
        const int nh = warp >> 3;
        const int rowBase = bb << 4;
        const int wrO = bb >> 1, iO = bb & 1;
        const uint32_t* M2 = (const uint32_t*)(matS + (bb << 8));
        uint32_t a0 = M2[g * 8 + t];
        uint32_t a1 = M2[(g + 8) * 8 + t];
        uint32_t a2 = M2[g * 8 + t + 4];
        uint32_t a3 = M2[(g + 8) * 8 + t + 4];
        const uint32_t* Cs2 = (const uint32_t*)CsH;
        if (bm + rowBase < M) {
#pragma unroll
            for (int nn2 = 0; nn2 < 8; nn2++) {
                int n0 = ((nh << 3) + nn2) << 3;
                int col = n0 + g;
                uint32_t b0r = Cs2[col * 68 + (rowBase >> 1) + t];
                uint32_t b1r = Cs2[col * 68 + (rowBase >> 1) + t + 4];
                float v0 = 0.f, v1 = 0.f, v2 = 0.f, v3 = 0.f;
                MMA16(v0, v1, v2, v3, a0, a1, a2, a3, b0r, b1r);
                int G = bnG + n0 + 2 * t;
                int chO = G >> 5, kk2 = G & 31;
                int ksO = kk2 >> 4, tposO = (kk2 >> 1) & 3, khO = (kk2 >> 3) & 1;
                size_t cb = (size_t)(tmO * nChOut + chO) * CHH;
                int ib = ((ksO * 4 + wrO) * 2 + iO) * 128 + (g * 4 + tposO) * 4 + khO * 2;
                *(__half2*)&Ch[cb + (size_t)ib * 2] =
                    __floats2half2_rn(v0, v1);          // row mbit0: cols G,G+1
                *(__half2*)&Ch[cb + (size_t)(ib + 1) * 2] =
                    __floats2half2_rn(v2, v3);          // row mbit1
            }
        }
        return;
    }

    // generic epilogue
#pragma unroll
    for (int i = 0; i < 2; i++) {
        int m0 = bm + (wr << 5) + (i << 4) + g;
#pragma unroll
        for (int j = 0; j < 4; j++) {
            int nl = (wc << 5) + (j << 3) + 2 * t;
            int n0 = bnG + nl;
#pragma unroll
            for (int rr = 0; rr < 2; rr++) {
                int m = m0 + rr * 8;
                if (m >= M) continue;
                float v0 = acc[i][j][rr * 2 + 0];
                float v1 = acc[i][j][rr * 2 + 1];
                int bc = bcol + nl;
                v0 += bsc * bias[bc];
                v1 += bsc * bias[bc + 1];
                if (resid) {
                    v0 += resid[(size_t)m * ldc + n0];
                    v1 += resid[(size_t)m * ldc + n0 + 1];
                }
                if (doGelu) {
                    v0 = 0.5f * v0 * (1.0f + erff(v0 * 0.70710678118654752f));
                    v1 = 0.5f * v1 * (1.0f + erff(v1 * 0.70710678118654752f));
                }
                if (outChunk) {
                    int chO = n0 >> 5, kk2 = n0 & 31;
                    int ksO = kk2 >> 4, tposO = (kk2 >> 1) & 3, khO = (kk2 >> 3) & 1;
                    size_t cb = (size_t)((m >> 7) * nChOut + chO) * CHH;
                    int ib = ((ksO * 4 + wr) * 2 + i) * 128 + (g * 4 + tposO) * 4 + khO * 2 + rr;
                    *(__half2*)&Ch[cb + (size_t)ib * 2] = __floats2half2_rn(v0, v1);
                } else {
                    *(float2*)(C + (size_t)m * ldc + n0) = make_float2(v0, v1);
                }
            }
        }
    }
}

// ---------------- launch ----------------
extern "C" void kernel_launch(void* const* d_in, const int* in_sizes, int n_in,
                              void* d_out, int out_size) {
    const float* x          = (const float*)d_in[0];
    const float* mask       = (const float*)d_in[1];
    const float* Wg         = (const float*)d_in[2];
    const float* bg         = (const float*)d_in[3];
    const float* log_scales = (const float*)d_in[4];
    const float* Wv         = (const float*)d_in[5];
    const float* bv         = (const float*)d_in[6];
    const float* We         = (const float*)d_in[7];
    const float* be         = (const float*)d_in[8];
    const float* Wo         = (const float*)d_in[9];
    const float* bo         = (const float*)d_in[10];
    const float* ln1g       = (const float*)d_in[11];
    const float* ln1b       = (const float*)d_in[12];
    const float* ln2g       = (const float*)d_in[13];
    const float* ln2b       = (const float*)d_in[14];
    const float* Wf1        = (const float*)d_in[15];
    const float* bf1        = (const float*)d_in[16];
    const float* Wf2        = (const float*)d_in[17];
    const float* bf2        = (const float*)d_in[18];
    float* out = (float*)d_out;

    int B = in_sizes[0] / (KNODES * DMODEL);
    int M = B * KNODES;
    int gy = (M + 127) / 128;

    void *p_xn, *p_P, *p_mats, *p_NE, *p_y, *p_h, *p_F, *p_Wc;
    cudaGetSymbolAddress(&p_xn, g_xn);
    cudaGetSymbolAddress(&p_P, g_P);
    cudaGetSymbolAddress(&p_mats, g_mats);
    cudaGetSymbolAddress(&p_NE, g_NE);
    cudaGetSymbolAddress(&p_y, g_y);
    cudaGetSymbolAddress(&p_h, g_h);
    cudaGetSymbolAddress(&p_F, g_F);
    cudaGetSymbolAddress(&p_Wc, g_Wc);
    __half* xn = (__half*)p_xn; float* Pm = (float*)p_P;
    float* mats = (float*)p_mats;
    __half* NE = (__half*)p_NE; float* y = (float*)p_y;
    __half* h = (__half*)p_h;   __half* F = (__half*)p_F;
    __half* Wc = (__half*)p_Wc;

    static int attrDone = 0;
    if (!attrDone) {
        cudaFuncSetAttribute(fp16_gemm, cudaFuncAttributeMaxDynamicSharedMemorySize, SMEM_BYTES);
        attrDone = 1;
    }
    const int BIGN = 1 << 28;

    convert_w_kernel<<<(WSRC + 255) / 256, 256>>>(Wv, We, Wo, Wf1, Wf2, Wc);
    ln1_p_kernel<<<M, 256>>>(x, ln1g, ln1b, Wg, bg, xn, Pm);
    build_mats_kernel<<<B, 256>>>(Pm, mask, log_scales, mats);
    // NE = blockdiag(16x16) x [xn@Wv + bv | xn@We + 0.5*be]  (fp16 chunks, 48 ch)
    fp16_gemm<<<dim3(12, gy), 512, SMEM_BYTES>>>(
        xn, Wc + OFF_WV, Wc + OFF_WE, 768,
        nullptr, NE, bv, be, 1.0f, 0.5f, nullptr, mats, 1,
        M, 8, 0, 1, 48, 0);
    // y = x + NE@Wo + bo  (fp32 row-major out)
    fp16_gemm<<<dim3(2, gy), 512, SMEM_BYTES>>>(
        NE, Wc + OFF_WO, Wc + OFF_WO, BIGN,
        y, nullptr, bo, bo, 1.0f, 1.0f, x, nullptr, 0,
        M, 48, 256, 0, 0, 0);
    ln_kernel<<<M, 256>>>(y, ln2g, ln2b, h);
    // F = gelu(h@Wf1 + bf1)  (fp16 chunks, 32 ch)
    fp16_gemm<<<dim3(8, gy), 512, SMEM_BYTES>>>(
        h, Wc + OFF_WF1, Wc + OFF_WF1, BIGN,
        nullptr, F, bf1, bf1, 1.0f, 1.0f, nullptr, nullptr, 0,
        M, 8, 0, 1, 32, 1);
    // out = y + F@Wf2 + bf2  (fp32 row-major out)
    fp16_gemm<<<dim3(2, gy), 512, SMEM_BYTES>>>(
        F, Wc + OFF_WF2, Wc + OFF_WF2, BIGN,
        out, nullptr, bf2, bf2, 1.0f, 1.0f, y, nullptr, 0,
        M, 32, 256, 0, 0, 0);
}

// round 17
// speedup vs baseline: 1.4450x; 1.0563x over previous
#include <cuda_runtime.h>
#include <cuda_fp16.h>
#include <cstdint>
#include <math.h>

#define KNODES 16
#define DMODEL 256
#define NSCALE 3
#define TAU_C 0.0001f
#define LN_EPS_C 1e-5f
#define MAXB 1024

// A- and B-chunks: 128(rows/cols) x 64(k) fp16 = 8192 halves = 16 KB, frag order
#define CHH 8192

// weight segment offsets in g_Wc (halves)
#define OFF_WV 0
#define OFF_WE 196608
#define OFF_WO 393216
#define OFF_WF1 786432
#define OFF_WF2 1048576
#define WSRC 1310720

__device__ __half g_xn[128 * 4 * CHH];
__device__ float  g_P [MAXB * KNODES * KNODES];
__device__ float  g_mats[MAXB * NSCALE * 2 * 256];
__device__ __half g_NE[(size_t)128 * 24 * CHH];
__device__ float  g_y [MAXB * KNODES * DMODEL];
__device__ __half g_h [128 * 4 * CHH];
__device__ __half g_F [(size_t)128 * 16 * CHH];
__device__ __half g_Wc[WSRC];

// ---------------- helpers ----------------
__device__ __forceinline__ uint32_t su32(const void* p) {
    return (uint32_t)__cvta_generic_to_shared(p);
}
__device__ __forceinline__ void bulk_g2s(uint32_t dst, const void* src,
                                         uint32_t bytes, uint32_t mbar) {
    asm volatile(
        "cp.async.bulk.shared::cluster.global.mbarrier::complete_tx::bytes [%0], [%1], %2, [%3];"
        :: "r"(dst), "l"(src), "r"(bytes), "r"(mbar) : "memory");
}
#define MBAR_INIT(mb, c)  asm volatile("mbarrier.init.shared.b64 [%0], %1;" :: "r"(mb), "r"(c) : "memory")
#define MBAR_EXPECT(mb, b) asm volatile("mbarrier.arrive.expect_tx.shared.b64 _, [%0], %1;" :: "r"(mb), "r"(b) : "memory")
#define MBAR_WAIT(mb, p) do { \
    uint32_t _m = (mb), _p = (p), _d; \
    asm volatile("{\n\t.reg .pred q;\n\t" \
        "mbarrier.try_wait.parity.acquire.cta.shared::cta.b64 q, [%1], %2;\n\t" \
        "selp.b32 %0, 1, 0, q;\n\t}" : "=r"(_d) : "r"(_m), "r"(_p) : "memory"); \
    if (!_d) asm volatile("{\n\t.reg .pred q;\n\t" \
        "WL_%=:\n\tmbarrier.try_wait.parity.acquire.cta.shared::cta.b64 q, [%0], %1, 0x989680;\n\t" \
        "@q bra.uni WD_%=;\n\tbra.uni WL_%=;\n\tWD_%=:\n\t}" :: "r"(_m), "r"(_p) : "memory"); \
} while (0)

#define MMA16(c0,c1,c2,c3, a0,a1,a2,a3, b0,b1) \
    asm volatile("mma.sync.aligned.m16n8k16.row.col.f32.f16.f16.f32 " \
        "{%0,%1,%2,%3}, {%4,%5,%6,%7}, {%8,%9}, {%0,%1,%2,%3};" \
        : "+f"(c0), "+f"(c1), "+f"(c2), "+f"(c3) \
        : "r"(a0), "r"(a1), "r"(a2), "r"(a3), "r"(b0), "r"(b1))

__device__ __forceinline__ float block_sum_256(float v) {
    __shared__ float red[8];
#pragma unroll
    for (int o = 16; o > 0; o >>= 1) v += __shfl_xor_sync(0xffffffffu, v, o);
    int lane = threadIdx.x & 31, w = threadIdx.x >> 5;
    if (lane == 0) red[w] = v;
    __syncthreads();
    float t = (threadIdx.x < 8) ? red[threadIdx.x] : 0.f;
    if (threadIdx.x < 32) {
#pragma unroll
        for (int o = 4; o > 0; o >>= 1) t += __shfl_xor_sync(0xffffffffu, t, o);
        if (threadIdx.x == 0) red[0] = t;
    }
    __syncthreads();
    float r = red[0];
    __syncthreads();
    return r;
}

// fp16 m16n8k16 fragment half-index for A element (r=row&127, kk=k&63)
__device__ __forceinline__ int afrag_idx(int r, int kk) {
    int ks = kk >> 4, tpos = (kk >> 1) & 3, khigh = (kk >> 3) & 1, par = kk & 1;
    int wr = r >> 5, i = (r >> 4) & 1, mbit = (r >> 3) & 1, gg = r & 7;
    return ((((ks * 4 + wr) * 2 + i) * 128 + (gg * 4 + tpos) * 4 + (khigh * 2 + mbit)) << 1) | par;
}
// B element (kk=k&63, nn=n&127)
__device__ __forceinline__ int bfrag_idx(int kk, int nn) {
    int ks = kk >> 4, tpos = (kk >> 1) & 3, khigh = (kk >> 3) & 1, par = kk & 1;
    int wc = nn >> 5, j = (nn >> 3) & 3, gg = nn & 7;
    return ((((ks * 4 + wc) * 4 + j) * 64 + (gg * 4 + tpos) * 2 + khigh) << 1) | par;
}

// ---------------- weights -> fragment-chunked fp16 ----------------
__global__ void convert_w_kernel(const float* __restrict__ Wv, const float* __restrict__ We,
                                 const float* __restrict__ Wo, const float* __restrict__ Wf1,
                                 const float* __restrict__ Wf2, __half* __restrict__ Wc) {
    int i = blockIdx.x * 256 + threadIdx.x;
    if (i >= WSRC) return;
    const float* src; int soff, doff, Kd, N;
    if (i < 196608)       { src = Wv;  soff = 0;       doff = OFF_WV;  Kd = 256;  N = 768;  }
    else if (i < 393216)  { src = We;  soff = 196608;  doff = OFF_WE;  Kd = 256;  N = 768;  }
    else if (i < 786432)  { src = Wo;  soff = 393216;  doff = OFF_WO;  Kd = 1536; N = 256;  }
    else if (i < 1048576) { src = Wf1; soff = 786432;  doff = OFF_WF1; Kd = 256;  N = 1024; }
    else                  { src = Wf2; soff = 1048576; doff = OFF_WF2; Kd = 1024; N = 256;  }
    int loc = i - soff;
    int k = loc / N, n = loc % N;
    int tn = n >> 7, ch = k >> 6;
    Wc[doff + (size_t)(tn * (Kd >> 6) + ch) * CHH + bfrag_idx(k & 63, n & 127)] =
        __float2half(src[loc]);
}

// ---------------- LN1 + P  (xn -> A-frag fp16 chunks) ----------------
__global__ void ln1_p_kernel(const float* __restrict__ x,
                             const float* __restrict__ g, const float* __restrict__ bb,
                             const float* __restrict__ Wg, const float* __restrict__ bg,
                             __half* __restrict__ xn_out, float* __restrict__ P_out) {
    int row = blockIdx.x;
    int t = threadIdx.x;
    float v = x[(size_t)row * DMODEL + t];
    float mean = block_sum_256(v) * (1.f / DMODEL);
    float d = v - mean;
    float var = block_sum_256(d * d) * (1.f / DMODEL);
    float xn = d * rsqrtf(var + LN_EPS_C) * g[t] + bb[t];
    int tm = row >> 7, r = row & 127, ch = t >> 6;
    xn_out[(size_t)(tm * 4 + ch) * CHH + afrag_idx(r, t & 63)] = __float2half(xn);

    __shared__ float sxn[256];
    __shared__ float part[256];
    sxn[t] = xn;
    __syncthreads();
    int c = t & 15, seg = t >> 4;
    float p = 0.f;
    int d0 = seg * 16;
#pragma unroll
    for (int i = 0; i < 16; i++) p += sxn[d0 + i] * Wg[(d0 + i) * 16 + c];
    part[seg * 16 + c] = p;
    __syncthreads();
    if (t < 16) {
        float acc = bg[t];
#pragma unroll
        for (int s = 0; s < 16; s++) acc += part[s * 16 + t];
        P_out[(size_t)row * 16 + t] = acc;
    }
}

// ---------------- LN2 (y row-major -> h fp16 A-frag chunks) ----------------
__global__ void ln_kernel(const float* __restrict__ x,
                          const float* __restrict__ g, const float* __restrict__ bb,
                          __half* __restrict__ out) {
    int row = blockIdx.x;
    int t = threadIdx.x;
    float v = x[(size_t)row * DMODEL + t];
    float mean = block_sum_256(v) * (1.f / DMODEL);
    float d = v - mean;
    float var = block_sum_256(d * d) * (1.f / DMODEL);
    int tm = row >> 7, r = row & 127, ch = t >> 6;
    out[(size_t)(tm * 4 + ch) * CHH + afrag_idx(r, t & 63)] =
        __float2half(d * rsqrtf(var + LN_EPS_C) * g[t] + bb[t]);
}

// ---------------- per-(b,s) 16x16 operators ----------------
__global__ void build_mats_kernel(const float* __restrict__ P,
                                  const float* __restrict__ mask,
                                  const float* __restrict__ log_scales,
                                  float* __restrict__ mats) {
    int b = blockIdx.x;
    int tid = threadIdx.x;
    __shared__ float sP[256], sm[16], sp2[16], sDsq[256], saff[256], stw[16];
    sP[tid] = P[(size_t)b * 256 + tid];
    if (tid < 16) sm[tid] = mask[(size_t)b * 16 + tid];
    __syncthreads();
    int k = tid >> 4, l = tid & 15;
    if (tid < 16) {
        float s = 0.f;
#pragma unroll
        for (int c = 0; c < 16; c++) s += sP[tid * 16 + c] * sP[tid * 16 + c];
        sp2[tid] = s;
    }
    __syncthreads();
    {
        float dt = 0.f;
#pragma unroll
        for (int c = 0; c < 16; c++) dt += sP[k * 16 + c] * sP[l * 16 + c];
        sDsq[tid] = fmaxf(sp2[k] + sp2[l] - 2.f * dt, 0.f) * sm[k] * sm[l];
    }
    __syncthreads();
    for (int s = 0; s < NSCALE; s++) {
        float denom = 2.f * expf(2.f * log_scales[s]) + 1e-8f;
        saff[tid] = expf(-sDsq[tid] / denom) * sm[k] * sm[l];
        __syncthreads();
        float l0;
        if (k == l) {
            float srow = 0.f;
#pragma unroll
            for (int j = 0; j < 16; j++) if (j != k) srow += saff[k * 16 + j];
            l0 = srow + TAU_C;
        } else l0 = -saff[tid];
        if (tid < 16) {
            float tsum = 0.f;
            int j = tid;
            for (int i = 0; i < j; i++)
                for (int k2 = j + 1; k2 < 16; k2++)
                    tsum += saff[i * 16 + j] * saff[j * 16 + k2] * saff[i * 16 + k2];
            stw[tid] = tsum;
        }
        __syncthreads();
        float nv = 0.f;
#pragma unroll
        for (int kp = 0; kp < 16; kp++) {
            float dk = (kp == k) ? (2.f * k - 15.f) : ((kp > k) ? 1.f : -1.f);
            float dl = (kp == l) ? (2.f * l - 15.f) : ((kp > l) ? 1.f : -1.f);
            nv += sm[kp] * dk * dl;
        }
        nv += (k == l) ? (4.f * stw[k] + 15.f * TAU_C) : TAU_C;
        size_t base = ((size_t)b * NSCALE + s) * 512;
        mats[base + tid] = l0;
        mats[base + 256 + tid] = nv;
        __syncthreads();
    }
}

// ---------------- fp16 mma GEMM: 512 thr, 16 warps of 32x32, K64 ring-3 -----
#define STAGE_BYTES 32768
#define STAGE_U32   8192
#define SMEM_BYTES  (3 * STAGE_BYTES)   // 98304

__global__ __launch_bounds__(512, 2) void fp16_gemm(
    const __half* __restrict__ A,
    const __half* __restrict__ B1, const __half* __restrict__ B2, int N1,
    float* __restrict__ C, __half* __restrict__ Ch,
    const float* __restrict__ bias1, const float* __restrict__ bias2,
    float s1, float s2,
    const float* __restrict__ resid,
    const float* __restrict__ matsG, int applyMats,
    int M, int nChK, int ldc, int outChunk, int nChOut, int doGelu)
{
    extern __shared__ uint32_t sm_[];
    __shared__ __align__(8) uint64_t mbarStore[3];

    const int tid  = threadIdx.x;
    const int warp = tid >> 5, lane = tid & 31;
    const int g = lane >> 2, t = lane & 3;
    const int wr = warp >> 2;
    const int wc = warp & 3;
    const int bm = blockIdx.y << 7;
    const int bnG = blockIdx.x << 7;
    const uint32_t base = su32(sm_);
    const uint32_t mbF = su32(&mbarStore[0]);

    const __half* Bseg; const float* bias; float bsc; int bcol;
    if (bnG < N1) { Bseg = B1; bias = bias1; bsc = s1; bcol = bnG; }
    else          { Bseg = B2; bias = bias2; bsc = s2; bcol = bnG - N1; }
    const __half* At = A + (size_t)(bm >> 7) * nChK * CHH;
    const __half* Bt = Bseg + (size_t)(bcol >> 7) * nChK * CHH;

    if (tid == 0)
        for (int i = 0; i < 3; i++) MBAR_INIT(mbF + 8 * i, 1);
    __syncthreads();

#define ISSUE(s_, ch_) do { \
    if (tid == 0) { \
        MBAR_EXPECT(mbF + 8 * (s_), (uint32_t)STAGE_BYTES); \
        bulk_g2s(base + (s_) * STAGE_BYTES, At + (size_t)(ch_) * CHH, CHH * 2, mbF + 8 * (s_)); \
        bulk_g2s(base + (s_) * STAGE_BYTES + CHH * 2, Bt + (size_t)(ch_) * CHH, CHH * 2, mbF + 8 * (s_)); \
    } \
} while (0)

    ISSUE(0, 0);
    if (nChK > 1) ISSUE(1, 1);

    float acc[2][4][4];
#pragma unroll
    for (int i = 0; i < 2; i++)
#pragma unroll
        for (int j = 0; j < 4; j++)
#pragma unroll
            for (int r = 0; r < 4; r++) acc[i][j][r] = 0.f;

    for (int ch = 0; ch < nChK; ch++) {
        const int s = ch % 3;
        MBAR_WAIT(mbF + 8 * s, (ch / 3) & 1);
        __syncthreads();
        if (ch + 2 < nChK) ISSUE((ch + 2) % 3, ch + 2);

        const uint4* As4 = (const uint4*)(sm_ + s * STAGE_U32);
        const uint2* Bs2 = (const uint2*)(sm_ + s * STAGE_U32 + 4096);

#pragma unroll
        for (int ks = 0; ks < 4; ks++) {
            uint4 av[2];
            uint2 bv[4];
#pragma unroll
            for (int i = 0; i < 2; i++)
                av[i] = As4[((ks * 4 + wr) * 2 + i) * 32 + lane];
#pragma unroll
            for (int j = 0; j < 4; j++)
                bv[j] = Bs2[((ks * 4 + wc) * 4 + j) * 32 + lane];
#pragma unroll
            for (int i = 0; i < 2; i++)
#pragma unroll
                for (int j = 0; j < 4; j++)
                    MMA16(acc[i][j][0], acc[i][j][1], acc[i][j][2], acc[i][j][3],
                          av[i].x, av[i].y, av[i].z, av[i].w, bv[j].x, bv[j].y);
        }
    }
#undef ISSUE

    const int tmO = bm >> 7;
    if (applyMats) {
        // fp16 tensor-core 16x16 Hodge apply:  out_b = M_b @ (acc_b + bias)
        __half* CsH = (__half*)sm_;                 // [col][136] halves
        __half* matS = (__half*)(sm_ + (128 * 136) / 2);
        __syncthreads();
#pragma unroll
        for (int i = 0; i < 2; i++) {
            int ml = (wr << 5) + (i << 4) + g;
#pragma unroll
            for (int j = 0; j < 4; j++) {
                int nl = (wc << 5) + (j << 3) + 2 * t;
                int bc = bcol + nl;
                float b0v = bsc * bias[bc];
                float b1v = bsc * bias[bc + 1];
#pragma unroll
                for (int rr = 0; rr < 2; rr++) {
                    int row = ml + rr * 8;
                    CsH[nl * 136 + row]       = __float2half(acc[i][j][rr * 2 + 0] + b0v);
                    CsH[(nl + 1) * 136 + row] = __float2half(acc[i][j][rr * 2 + 1] + b1v);
                }
            }
        }
        int isN = (bnG >= 768) ? 1 : 0;
        int sgrp = (isN ? (bnG - 768) : bnG) >> 8;
        int b0 = bm >> 4;
        for (int i = tid; i < 2048; i += 512) {
            int bb2 = i >> 8, e = i & 255;
            matS[i] = __float2half(
                matsG[((size_t)(b0 + bb2) * NSCALE + sgrp) * 512 + (isN << 8) + e]);
        }
        __syncthreads();
        const int bb = warp & 7;
        const int nh = warp >> 3;
        const int rowBase = bb << 4;
        const int wrO = bb >> 1, iO = bb & 1;
        const uint32_t* M2 = (const uint32_t*)(matS + (bb << 8));
        uint32_t a0 = M2[g * 8 + t];
        uint32_t a1 = M2[(g + 8) * 8 + t];
        uint32_t a2 = M2[g * 8 + t + 4];
        uint32_t a3 = M2[(g + 8) * 8 + t + 4];
        const uint32_t* Cs2 = (const uint32_t*)CsH;
        if (bm + rowBase < M) {
#pragma unroll
            for (int nn2 = 0; nn2 < 8; nn2++) {
                int n0 = ((nh << 3) + nn2) << 3;
                int col = n0 + g;
                uint32_t b0r = Cs2[col * 68 + (rowBase >> 1) + t];
                uint32_t b1r = Cs2[col * 68 + (rowBase >> 1) + t + 4];
                float v0 = 0.f, v1 = 0.f, v2 = 0.f, v3 = 0.f;
                MMA16(v0, v1, v2, v3, a0, a1, a2, a3, b0r, b1r);
                int G = bnG + n0 + 2 * t;
                int chO = G >> 6, kk2 = G & 63;
                int ksO = kk2 >> 4, tposO = (kk2 >> 1) & 3, khO = (kk2 >> 3) & 1;
                size_t cb = (size_t)(tmO * nChOut + chO) * CHH;
                int ib = ((ksO * 4 + wrO) * 2 + iO) * 128 + (g * 4 + tposO) * 4 + khO * 2;
                *(__half2*)&Ch[cb + (size_t)ib * 2] =
                    __floats2half2_rn(v0, v1);          // row mbit0: cols G,G+1
                *(__half2*)&Ch[cb + (size_t)(ib + 1) * 2] =
                    __floats2half2_rn(v2, v3);          // row mbit1
            }
        }
        return;
    }

    // generic epilogue
#pragma unroll
    for (int i = 0; i < 2; i++) {
        int m0 = bm + (wr << 5) + (i << 4) + g;
#pragma unroll
        for (int j = 0; j < 4; j++) {
            int nl = (wc << 5) + (j << 3) + 2 * t;
            int n0 = bnG + nl;
#pragma unroll
            for (int rr = 0; rr < 2; rr++) {
                int m = m0 + rr * 8;
                if (m >= M) continue;
                float v0 = acc[i][j][rr * 2 + 0];
                float v1 = acc[i][j][rr * 2 + 1];
                int bc = bcol + nl;
                v0 += bsc * bias[bc];
                v1 += bsc * bias[bc + 1];
                if (resid) {
                    v0 += resid[(size_t)m * ldc + n0];
                    v1 += resid[(size_t)m * ldc + n0 + 1];
                }
                if (doGelu) {
                    v0 = 0.5f * v0 * (1.0f + erff(v0 * 0.70710678118654752f));
                    v1 = 0.5f * v1 * (1.0f + erff(v1 * 0.70710678118654752f));
                }
                if (outChunk) {
                    int chO = n0 >> 6, kk2 = n0 & 63;
                    int ksO = kk2 >> 4, tposO = (kk2 >> 1) & 3, khO = (kk2 >> 3) & 1;
                    size_t cb = (size_t)((m >> 7) * nChOut + chO) * CHH;
                    int ib = ((ksO * 4 + wr) * 2 + i) * 128 + (g * 4 + tposO) * 4 + khO * 2 + rr;
                    *(__half2*)&Ch[cb + (size_t)ib * 2] = __floats2half2_rn(v0, v1);
                } else {
                    *(float2*)(C + (size_t)m * ldc + n0) = make_float2(v0, v1);
                }
            }
        }
    }
}

// ---------------- launch ----------------
extern "C" void kernel_launch(void* const* d_in, const int* in_sizes, int n_in,
                              void* d_out, int out_size) {
    const float* x          = (const float*)d_in[0];
    const float* mask       = (const float*)d_in[1];
    const float* Wg         = (const float*)d_in[2];
    const float* bg         = (const float*)d_in[3];
    const float* log_scales = (const float*)d_in[4];
    const float* Wv         = (const float*)d_in[5];
    const float* bv         = (const float*)d_in[6];
    const float* We         = (const float*)d_in[7];
    const float* be         = (const float*)d_in[8];
    const float* Wo         = (const float*)d_in[9];
    const float* bo         = (const float*)d_in[10];
    const float* ln1g       = (const float*)d_in[11];
    const float* ln1b       = (const float*)d_in[12];
    const float* ln2g       = (const float*)d_in[13];
    const float* ln2b       = (const float*)d_in[14];
    const float* Wf1        = (const float*)d_in[15];
    const float* bf1        = (const float*)d_in[16];
    const float* Wf2        = (const float*)d_in[17];
    const float* bf2        = (const float*)d_in[18];
    float* out = (float*)d_out;

    int B = in_sizes[0] / (KNODES * DMODEL);
    int M = B * KNODES;
    int gy = (M + 127) / 128;

    void *p_xn, *p_P, *p_mats, *p_NE, *p_y, *p_h, *p_F, *p_Wc;
    cudaGetSymbolAddress(&p_xn, g_xn);
    cudaGetSymbolAddress(&p_P, g_P);
    cudaGetSymbolAddress(&p_mats, g_mats);
    cudaGetSymbolAddress(&p_NE, g_NE);
    cudaGetSymbolAddress(&p_y, g_y);
    cudaGetSymbolAddress(&p_h, g_h);
    cudaGetSymbolAddress(&p_F, g_F);
    cudaGetSymbolAddress(&p_Wc, g_Wc);
    __half* xn = (__half*)p_xn; float* Pm = (float*)p_P;
    float* mats = (float*)p_mats;
    __half* NE = (__half*)p_NE; float* y = (float*)p_y;
    __half* h = (__half*)p_h;   __half* F = (__half*)p_F;
    __half* Wc = (__half*)p_Wc;

    static int attrDone = 0;
    if (!attrDone) {
        cudaFuncSetAttribute(fp16_gemm, cudaFuncAttributeMaxDynamicSharedMemorySize, SMEM_BYTES);
        attrDone = 1;
    }
    const int BIGN = 1 << 28;

    convert_w_kernel<<<(WSRC + 255) / 256, 256>>>(Wv, We, Wo, Wf1, Wf2, Wc);
    ln1_p_kernel<<<M, 256>>>(x, ln1g, ln1b, Wg, bg, xn, Pm);
    build_mats_kernel<<<B, 256>>>(Pm, mask, log_scales, mats);
    // NE = blockdiag(16x16) x [xn@Wv + bv | xn@We + 0.5*be]  (fp16 chunks, 24 ch)
    fp16_gemm<<<dim3(12, gy), 512, SMEM_BYTES>>>(
        xn, Wc + OFF_WV, Wc + OFF_WE, 768,
        nullptr, NE, bv, be, 1.0f, 0.5f, nullptr, mats, 1,
        M, 4, 0, 1, 24, 0);
    // y = x + NE@Wo + bo  (fp32 row-major out)
    fp16_gemm<<<dim3(2, gy), 512, SMEM_BYTES>>>(
        NE, Wc + OFF_WO, Wc + OFF_WO, BIGN,
        y, nullptr, bo, bo, 1.0f, 1.0f, x, nullptr, 0,
        M, 24, 256, 0, 0, 0);
    ln_kernel<<<M, 256>>>(y, ln2g, ln2b, h);
    // F = gelu(h@Wf1 + bf1)  (fp16 chunks, 16 ch)
    fp16_gemm<<<dim3(8, gy), 512, SMEM_BYTES>>>(
        h, Wc + OFF_WF1, Wc + OFF_WF1, BIGN,
        nullptr, F, bf1, bf1, 1.0f, 1.0f, nullptr, nullptr, 0,
        M, 4, 0, 1, 16, 1);
    // out = y + F@Wf2 + bf2  (fp32 row-major out)
    fp16_gemm<<<dim3(2, gy), 512, SMEM_BYTES>>>(
        F, Wc + OFF_WF2, Wc + OFF_WF2, BIGN,
        out, nullptr, bf2, bf2, 1.0f, 1.0f, y, nullptr, 0,
        M, 16, 256, 0, 0, 0);
}